// round 13
// baseline (speedup 1.0000x reference)
#include <cuda_runtime.h>
#include <cuda_fp16.h>
#include <math.h>
#include <stdint.h>

#define Bc 2
#define Sc 2048
#define Ec 1024
#define NHc 4
#define DHc 256
#define BH  8
#define KT  64
#define NRT 32
#define NTILES 256

// ------------------------- device scratch -------------------------
__device__ float g_ig [BH*Sc];
__device__ float g_lsf[BH*Sc];
__device__ float g_m  [BH*Sc];
__device__ float g_pm [BH*Sc];
__device__ float g_mld[BH*Sc];
__device__ float g_ct [BH*NRT];
__device__ __half g_qh[(size_t)BH*Sc*DHc];
__device__ __half g_kh[(size_t)BH*Sc*DHc];
__device__ __half g_vh[(size_t)BH*Sc*DHc];
__device__ int g_tile_ctr;

// ------------------------- helpers -------------------------
__device__ __forceinline__ uint32_t smem_u32(const void* p) {
    uint32_t a;
    asm("{ .reg .u64 t; cvta.to.shared.u64 t, %1; cvt.u32.u64 %0, t; }" : "=r"(a) : "l"(p));
    return a;
}
__device__ __forceinline__ void ldsm4(uint32_t* r, uint32_t a) {
    asm volatile("ldmatrix.sync.aligned.m8n8.x4.shared.b16 {%0,%1,%2,%3}, [%4];"
        : "=r"(r[0]), "=r"(r[1]), "=r"(r[2]), "=r"(r[3]) : "r"(a));
}
__device__ __forceinline__ void ldsm4t(uint32_t* r, uint32_t a) {
    asm volatile("ldmatrix.sync.aligned.m8n8.x4.trans.shared.b16 {%0,%1,%2,%3}, [%4];"
        : "=r"(r[0]), "=r"(r[1]), "=r"(r[2]), "=r"(r[3]) : "r"(a));
}
__device__ __forceinline__ void mma16816(float* c, const uint32_t* a, const uint32_t* b) {
    asm volatile("mma.sync.aligned.m16n8k16.row.col.f32.f16.f16.f32 "
        "{%0,%1,%2,%3}, {%4,%5,%6,%7}, {%8,%9}, {%0,%1,%2,%3};"
        : "+f"(c[0]), "+f"(c[1]), "+f"(c[2]), "+f"(c[3])
        : "r"(a[0]), "r"(a[1]), "r"(a[2]), "r"(a[3]), "r"(b[0]), "r"(b[1]));
}
__device__ __forceinline__ uint32_t pkh2(float lo, float hi) {
    uint32_t r; asm("cvt.rn.f16x2.f32 %0, %1, %2;" : "=r"(r) : "f"(hi), "f"(lo)); return r;
}
__device__ __forceinline__ void cpa16(uint32_t s, const void* g) {
    asm volatile("cp.async.cg.shared.global [%0], [%1], 16;" :: "r"(s), "l"(g));
}
#define CP_COMMIT() asm volatile("cp.async.commit_group;" ::: "memory")
#define CP_WAIT0()  asm volatile("cp.async.wait_group 0;" ::: "memory")
#define CP_WAIT1()  asm volatile("cp.async.wait_group 1;" ::: "memory")

// stage a 64x256-half tile into swizzled smem (512B rows, chunk^(row&7))
__device__ __forceinline__ void stage_tile(uint32_t dst, const __half* src, int tid) {
    #pragma unroll
    for (int it = 0; it < 8; ++it) {
        int lin = tid + it * 256;
        int row = lin >> 5, d8 = lin & 31;
        uint32_t o = dst + row * 512 + (uint32_t)((d8 ^ (row & 7)) << 4);
        cpa16(o, src + (size_t)row * 256 + d8 * 8);
    }
}

// ---------------------------------------------------------------------------
// gates: smem-cached weights; writes q,k,v fp16 (head-split) on the fly.
// 2 rows/warp, 2 CTAs/SM.
// ---------------------------------------------------------------------------
#define GATES_SMEM (24576 * 4)
__global__ __launch_bounds__(256, 2) void gates_kernel(
    const float* __restrict__ q, const float* __restrict__ k, const float* __restrict__ v,
    const float* __restrict__ igw, const float* __restrict__ igb,
    const float* __restrict__ fgw, const float* __restrict__ fgb)
{
    extern __shared__ float ws[];
    int tid  = threadIdx.x;
    int warp = tid >> 5;
    int lane = tid & 31;

    #pragma unroll
    for (int it = 0; it < 24; ++it) {
        int idx = tid + it * 256;
        float4 val = (idx < 3072) ? ((const float4*)igw)[idx]
                                  : ((const float4*)fgw)[idx - 3072];
        ((float4*)ws)[idx] = val;
    }
    __syncthreads();

    int row0 = blockIdx.x * 16 + warp * 2;
    float acc[2][8];
    #pragma unroll
    for (int r = 0; r < 2; ++r)
        #pragma unroll
        for (int c = 0; c < 8; ++c) acc[r][c] = 0.f;

    #pragma unroll
    for (int part = 0; part < 3; ++part) {
        const float* bp = (part == 0) ? q : (part == 1) ? k : v;
        __half* outh    = (part == 0) ? g_qh : (part == 1) ? g_kh : g_vh;
        #pragma unroll
        for (int it = 0; it < 8; ++it) {
            int f  = it * 128 + lane * 4;
            int wf = part * 1024 + f;
            float4 wi[4], wg_[4];
            #pragma unroll
            for (int h = 0; h < 4; ++h) {
                wi[h]  = *(const float4*)(ws + h * 3072 + wf);
                wg_[h] = *(const float4*)(ws + 12288 + h * 3072 + wf);
            }
            #pragma unroll
            for (int r = 0; r < 2; ++r) {
                int row = row0 + r;
                float4 x = *(const float4*)(bp + (size_t)row * Ec + f);
                #pragma unroll
                for (int h = 0; h < 4; ++h) {
                    acc[r][h]     += x.x*wi[h].x  + x.y*wi[h].y  + x.z*wi[h].z  + x.w*wi[h].w;
                    acc[r][h + 4] += x.x*wg_[h].x + x.y*wg_[h].y + x.z*wg_[h].z + x.w*wg_[h].w;
                }
                int bb = row >> 11, s = row & (Sc - 1);
                int hh = f >> 8, dd = f & 255;
                __half* dst = outh + ((size_t)(bb * NHc + hh) * Sc + s) * DHc + dd;
                ((__half2*)dst)[0] = __floats2half2_rn(x.x, x.y);
                ((__half2*)dst)[1] = __floats2half2_rn(x.z, x.w);
            }
        }
    }
    #pragma unroll
    for (int o = 16; o; o >>= 1)
        #pragma unroll
        for (int r = 0; r < 2; ++r)
            #pragma unroll
            for (int c = 0; c < 8; ++c)
                acc[r][c] += __shfl_xor_sync(0xffffffffu, acc[r][c], o);

    if (lane < 16) {
        int r = lane >> 3, c = lane & 7;
        float val = 0.f;
        #pragma unroll
        for (int rr = 0; rr < 2; ++rr)
            #pragma unroll
            for (int cc = 0; cc < 8; ++cc)
                if (rr == r && cc == c) val = acc[rr][cc];

        int row = row0 + r;
        int b = row >> 11;
        int s = row & (Sc - 1);
        if (c < 4) {
            g_ig[(b * NHc + c) * Sc + s] = val + igb[c];
        } else {
            int h = c - 4;
            float fgv = val + fgb[h];
            float lsf = fminf(fgv, 0.f) - log1pf(expf(-fabsf(fgv)));
            g_lsf[(b * NHc + h) * Sc + s] = lsf;
        }
    }
}

// ---------------------------------------------------------------------------
// scan: cumsum, m, per-64-tile max, prefix-max, mld; resets tile counter
// ---------------------------------------------------------------------------
__global__ __launch_bounds__(1024) void scan_kernel()
{
    __shared__ float s_a[2048];
    __shared__ float s_b[2048];
    __shared__ float s_cs[2048];

    int bh = blockIdx.x;
    int t  = threadIdx.x;
    const int base = bh * Sc;

    if (bh == 0 && t == 0) g_tile_ctr = 0;

    s_a[t]        = g_lsf[base + t];
    s_a[t + 1024] = g_lsf[base + t + 1024];
    __syncthreads();

    float* src = s_a; float* dst = s_b;
    for (int off = 1; off < 2048; off <<= 1) {
        #pragma unroll
        for (int u = 0; u < 2; ++u) {
            int i = t + (u << 10);
            float val = src[i];
            if (i >= off) val += src[i - off];
            dst[i] = val;
        }
        __syncthreads();
        float* tmp = src; src = dst; dst = tmp;
    }
    s_cs[t]        = src[t];
    s_cs[t + 1024] = src[t + 1024];
    __syncthreads();

    #pragma unroll
    for (int u = 0; u < 2; ++u) {
        int i = t + (u << 10);
        float m = g_ig[base + i] - (i > 0 ? s_cs[i - 1] : 0.f);
        g_m[base + i] = m;
        s_a[i] = m;
    }
    __syncthreads();

    if (t < NRT) {
        float mx = -1e30f;
        #pragma unroll 4
        for (int i = 0; i < KT; ++i) mx = fmaxf(mx, s_a[t * KT + i]);
        g_ct[bh * NRT + t] = mx;
    }
    __syncthreads();

    src = s_a; dst = s_b;
    for (int off = 1; off < 2048; off <<= 1) {
        #pragma unroll
        for (int u = 0; u < 2; ++u) {
            int i = t + (u << 10);
            float val = src[i];
            if (i >= off) val = fmaxf(val, src[i - off]);
            dst[i] = val;
        }
        __syncthreads();
        float* tmp = src; src = dst; dst = tmp;
    }
    #pragma unroll
    for (int u = 0; u < 2; ++u) {
        int i = t + (u << 10);
        g_pm[base + i]  = src[i];
        g_mld[base + i] = s_cs[i] + src[i];
    }
}

// ---------------------------------------------------------------------------
// attention: HMMA, persistent CTAs (LPT stealing), interleaved QK(jt)+PV(jt-1),
// K x2 / V x3 / P x2 buffers, cf decay table; qa reduced to 32 regs so ptxas
// has slack to software-pipeline ldsm ahead of mma.
// ---------------------------------------------------------------------------
#define OQ_  0
#define OK0  32768
#define OK1  65536
#define OV0  98304
#define OV1  131072
#define OV2  163840
#define OPS0 196608
#define OPS1 205824
#define ORS  215040
#define OINV 215552
#define OCT  215808
#define OTIL 215936
#define OCF  216064
#define SMEM_BYTES (216064 + 512)

__global__ __launch_bounds__(256, 1) void attn_kernel(
    const float* __restrict__ out_w, float* __restrict__ out)
{
    extern __shared__ char smb[];
    const uint32_t sb = smem_u32(smb);

    float* rsA  = (float*)(smb + ORS);
    float* sinv = (float*)(smb + OINV);
    float* sct  = (float*)(smb + OCT);
    int*  stile = (int*)(smb + OTIL);

    const int tid  = threadIdx.x;
    const int wid  = tid >> 5;
    const int lane = tid & 31;

    const int wm = wid & 3;        // m-tile (16 rows)
    const int wn = wid >> 2;       // key half (QK) / dh half (PV)
    const int m0 = wm * 16;
    const int g  = lane >> 2;
    const int tg = lane & 3;
    const int s7 = lane & 7;       // swizzle key

    const int lrow8 = (lane & 7) + 8 * ((lane >> 3) & 1);
    const int lcol8 = (lane >> 4);
    const int bq8   = (lane >> 3);

    const uint32_t vbuf[3] = { sb + OV0, sb + OV1, sb + OV2 };
    const uint32_t kbuf[2] = { sb + OK0, sb + OK1 };
    const uint32_t pbuf[2] = { sb + OPS0, sb + OPS1 };
    const uint32_t pabase0 = ((uint32_t)(m0 + lrow8) * 72 + (uint32_t)lcol8 * 8) * 2;

    for (;;) {
        if (tid == 0) *stile = atomicAdd(&g_tile_ctr, 1);
        __syncthreads();
        const int n = *stile;
        if (n >= NTILES) break;

        const int rt = 31 - (n >> 3);     // largest tiles first
        const int bh = n & 7;
        const int r0 = rt * KT;
        const int b = bh >> 2, h = bh & 3;

        const __half* qG = g_qh + (size_t)bh * Sc * DHc;
        const __half* kG = g_kh + (size_t)bh * Sc * DHc;
        const __half* vG = g_vh + (size_t)bh * Sc * DHc;

        if (tid < NRT) sct[tid] = g_ct[bh * NRT + tid];
        if (tid < 64)
            ((float*)(smb + OCF))[tid] =
                0.0625f * __expf(g_m[bh * Sc + tid] - g_ct[bh * NRT]);

        stage_tile(sb + OQ_, qG + (size_t)r0 * DHc, tid);
        stage_tile(kbuf[0], kG, tid);
        CP_COMMIT();                       // group: Q + K(0)
        stage_tile(vbuf[0], vG, tid);
        CP_COMMIT();                       // group: V(0)

        const float pm_g  = g_pm[bh * Sc + r0 + m0 + g];
        const float pm_g8 = g_pm[bh * Sc + r0 + m0 + g + 8];
        float rs0 = 0.f, rs1 = 0.f;
        float o_[64];
        #pragma unroll
        for (int i = 0; i < 64; ++i) o_[i] = 0.f;
        uint32_t qa[32];   // Q frags for dh 0..127 only (ks2 0..3)

        const uint32_t qrbase = sb + OQ_ + (uint32_t)(m0 + lrow8) * 512;

        for (int jt = 0; jt <= rt; ++jt) {
            const int t0 = jt * KT;
            const uint32_t okb = kbuf[jt & 1];

            CP_WAIT1();          // K(jt) + V(jt-1) arrived; V(jt) may still fly
            __syncthreads();

            if (jt < rt) {
                stage_tile(kbuf[(jt + 1) & 1], kG + (size_t)(t0 + KT) * DHc, tid);
                CP_COMMIT();
                stage_tile(vbuf[(jt + 1) % 3], vG + (size_t)(t0 + KT) * DHc, tid);
                CP_COMMIT();
                if (tid < 64)
                    ((float*)(smb + OCF + (((jt + 1) & 1) << 8)))[tid] =
                        0.0625f * __expf(g_m[bh * Sc + t0 + KT + tid] - sct[jt + 1]);
            }

            if (jt == 0) {
                #pragma unroll
                for (int ks = 0; ks < 8; ++ks)
                    ldsm4(qa + 4 * ks, qrbase + (uint32_t)(((lcol8 + 2 * ks) ^ s7) << 4));
            }

            // ======= INTERLEAVED: QK(jt) + PV(jt-1) =======
            float c[16];
            #pragma unroll
            for (int i = 0; i < 16; ++i) c[i] = 0.f;

            const bool havePV = (jt > 0);
            const uint32_t pab = pbuf[(jt + 1) & 1] + pabase0;  // (jt-1)&1
            const uint32_t ovb = vbuf[(jt + 2) % 3];            // (jt-1)%3
            uint32_t pa[4];

            #pragma unroll
            for (int ks2 = 0; ks2 < 8; ++ks2) {
                uint32_t aq[8];
                const uint32_t* af;
                if (ks2 < 4) {
                    af = qa + 8 * ks2;
                } else {
                    ldsm4(aq,     qrbase + (uint32_t)(((lcol8 + 4 * ks2)     ^ s7) << 4));
                    ldsm4(aq + 4, qrbase + (uint32_t)(((lcol8 + 4 * ks2 + 2) ^ s7) << 4));
                    af = aq;
                }
                #pragma unroll
                for (int nt = 0; nt < 4; ++nt) {
                    uint32_t bb[4];
                    uint32_t addr = okb + (uint32_t)(32 * wn + nt * 8 + s7) * 512
                                  + (uint32_t)((((ks2 << 2) + bq8) ^ s7) << 4);
                    ldsm4(bb, addr);
                    mma16816(c + 4 * nt, af,     bb);
                    mma16816(c + 4 * nt, af + 4, bb + 2);
                }
                if (havePV) {
                    int kst = ks2 >> 1;
                    int hh  = ks2 & 1;
                    if (hh == 0) ldsm4(pa, pab + (uint32_t)kst * 32);
                    uint32_t vrow = ovb + (uint32_t)(lrow8 + kst * 16) * 512;
                    #pragma unroll
                    for (int nn = 0; nn < 4; ++nn) {
                        int ntp = hh * 4 + nn;
                        uint32_t vb[4];
                        ldsm4t(vb, vrow + (uint32_t)(((wn * 16 + ntp * 2 + lcol8) ^ s7) << 4));
                        mma16816(o_ + 4 * (2 * ntp),     pa, vb);
                        mma16816(o_ + 4 * (2 * ntp + 1), pa, vb + 2);
                    }
                }
            }

            // ---------------- epilogue (tile jt): decay via cf, mask, pack P ----------------
            {
                char* psb = smb + (pbuf[jt & 1] - sb);
                const float* cf = (const float*)(smb + OCF + ((jt & 1) << 8));
                float ag  = __expf(sct[jt] - pm_g);
                float ag8 = __expf(sct[jt] - pm_g8);
                bool diag = (jt == rt);
                int rowg = r0 + m0 + g;
                #pragma unroll
                for (int nt = 0; nt < 4; ++nt) {
                    int cl  = 32 * wn + nt * 8 + 2 * tg;
                    int col = t0 + cl;
                    float2 ev = *(const float2*)(cf + cl);
                    float v0 = c[4*nt+0] * ev.x * ag;
                    float v1 = c[4*nt+1] * ev.y * ag;
                    float v2 = c[4*nt+2] * ev.x * ag8;
                    float v3 = c[4*nt+3] * ev.y * ag8;
                    if (diag) {
                        if (col     > rowg)     v0 = 0.f;
                        if (col + 1 > rowg)     v1 = 0.f;
                        if (col     > rowg + 8) v2 = 0.f;
                        if (col + 1 > rowg + 8) v3 = 0.f;
                    }
                    rs0 += v0 + v1;
                    rs1 += v2 + v3;
                    *(uint32_t*)(psb + ((m0 + g)     * 72 + cl) * 2) = pkh2(v0, v1);
                    *(uint32_t*)(psb + ((m0 + g + 8) * 72 + cl) * 2) = pkh2(v2, v3);
                }
            }
        } // jt

        CP_WAIT0();        // V(rt) definitely arrived
        __syncthreads();   // all warps wrote P(rt); V visible

        // ---------------- final P @ V (tile rt) ----------------
        {
            uint32_t pab = pbuf[rt & 1] + pabase0;
            uint32_t ovb = vbuf[rt % 3];
            #pragma unroll
            for (int kst = 0; kst < 4; ++kst) {
                uint32_t pa[4];
                ldsm4(pa, pab + (uint32_t)kst * 32);
                uint32_t vrow = ovb + (uint32_t)(lrow8 + kst * 16) * 512;
                #pragma unroll
                for (int ntp = 0; ntp < 8; ++ntp) {
                    uint32_t vb[4];
                    ldsm4t(vb, vrow + (uint32_t)(((wn * 16 + ntp * 2 + lcol8) ^ s7) << 4));
                    mma16816(o_ + 4 * (2 * ntp),     pa, vb);
                    mma16816(o_ + 4 * (2 * ntp + 1), pa, vb + 2);
                }
            }
        }

        // ---------------- rowsum reduce + normalizer ----------------
        rs0 += __shfl_xor_sync(0xffffffffu, rs0, 1);
        rs0 += __shfl_xor_sync(0xffffffffu, rs0, 2);
        rs1 += __shfl_xor_sync(0xffffffffu, rs1, 1);
        rs1 += __shfl_xor_sync(0xffffffffu, rs1, 2);
        if (tg == 0) {
            rsA[wn * 64 + m0 + g]     = rs0;
            rsA[wn * 64 + m0 + g + 8] = rs1;
        }
        __syncthreads();
        if (tid < 64) {
            float s = rsA[tid] + rsA[64 + tid];
            float nrm = fmaxf(fabsf(s), __expf(-g_mld[bh * Sc + r0 + tid])) + 1e-8f;
            sinv[tid] = 1.f / nrm;
        }
        __syncthreads();

        // ---------------- O -> H staging (f32, stride 260) ----------------
        {
            float* H = (float*)smb;
            float ivg  = sinv[m0 + g];
            float ivg8 = sinv[m0 + g + 8];
            #pragma unroll
            for (int nt = 0; nt < 16; ++nt) {
                int col = wn * 128 + nt * 8 + 2 * tg;
                H[(m0 + g)     * 260 + col]     = o_[4*nt+0] * ivg;
                H[(m0 + g)     * 260 + col + 1] = o_[4*nt+1] * ivg;
                H[(m0 + g + 8) * 260 + col]     = o_[4*nt+2] * ivg8;
                H[(m0 + g + 8) * 260 + col + 1] = o_[4*nt+3] * ivg8;
            }
        }
        __syncthreads();

        // ---------------- LayerNorm + affine + store ----------------
        {
            const float* H = (const float*)smb;
            int r  = tid >> 2;
            int qd = tid & 3;
            const float* hrow = H + r * 260 + qd * 64;
            float s1 = 0.f;
            #pragma unroll
            for (int i = 0; i < 16; ++i) {
                float4 x = *(const float4*)(hrow + i * 4);
                s1 += x.x + x.y + x.z + x.w;
            }
            s1 += __shfl_xor_sync(0xffffffffu, s1, 1);
            s1 += __shfl_xor_sync(0xffffffffu, s1, 2);
            float mean = s1 * (1.f / 256.f);
            float s2 = 0.f;
            #pragma unroll
            for (int i = 0; i < 16; ++i) {
                float4 x = *(const float4*)(hrow + i * 4);
                float d0 = x.x - mean, d1 = x.y - mean, d2 = x.z - mean, d3 = x.w - mean;
                s2 += d0*d0 + d1*d1 + d2*d2 + d3*d3;
            }
            s2 += __shfl_xor_sync(0xffffffffu, s2, 1);
            s2 += __shfl_xor_sync(0xffffffffu, s2, 2);
            float rstd = rsqrtf(s2 * (1.f / 256.f) + 1e-5f);

            float* dst = out + ((size_t)b * Sc + r0 + r) * Ec + h * DHc + qd * 64;
            const float* ow = out_w + h * DHc + qd * 64;
            #pragma unroll
            for (int i = 0; i < 16; ++i) {
                float4 x = *(const float4*)(hrow + i * 4);
                float4 w = *(const float4*)(ow + i * 4);
                float4 y;
                y.x = (x.x - mean) * rstd * (1.f + w.x);
                y.y = (x.y - mean) * rstd * (1.f + w.y);
                y.z = (x.z - mean) * rstd * (1.f + w.z);
                y.w = (x.w - mean) * rstd * (1.f + w.w);
                *(float4*)(dst + i * 4) = y;
            }
        }
        __syncthreads();
    } // tile loop
}

// ---------------------------------------------------------------------------
extern "C" void kernel_launch(void* const* d_in, const int* in_sizes, int n_in,
                              void* d_out, int out_size)
{
    const float* q   = (const float*)d_in[0];
    const float* k   = (const float*)d_in[1];
    const float* v   = (const float*)d_in[2];
    const float* igw = (const float*)d_in[3];
    const float* igb = (const float*)d_in[4];
    const float* fgw = (const float*)d_in[5];
    const float* fgb = (const float*)d_in[6];
    const float* ow  = (const float*)d_in[7];
    float* out = (float*)d_out;

    cudaFuncSetAttribute(attn_kernel, cudaFuncAttributeMaxDynamicSharedMemorySize, SMEM_BYTES);
    cudaFuncSetAttribute(gates_kernel, cudaFuncAttributeMaxDynamicSharedMemorySize, GATES_SMEM);

    gates_kernel<<<(Bc * Sc) / 16, 256, GATES_SMEM>>>(q, k, v, igw, igb, fgw, fgb);
    scan_kernel<<<BH, 1024>>>();
    attn_kernel<<<148, 256, SMEM_BYTES>>>(ow, out);
}

// round 14
// speedup vs baseline: 1.0703x; 1.0703x over previous
#include <cuda_runtime.h>
#include <cuda_fp16.h>
#include <math.h>
#include <stdint.h>

#define Bc 2
#define Sc 2048
#define Ec 1024
#define NHc 4
#define DHc 256
#define BH  8
#define KT  64
#define NRT 32
#define NTILES 256

// ------------------------- device scratch -------------------------
__device__ float g_ig [BH*Sc];
__device__ float g_lsf[BH*Sc];
__device__ float g_m  [BH*Sc];
__device__ float g_pm [BH*Sc];
__device__ float g_mld[BH*Sc];
__device__ float g_ct [BH*NRT];
__device__ __half g_qh[(size_t)BH*Sc*DHc];
__device__ __half g_kh[(size_t)BH*Sc*DHc];
__device__ __half g_vh[(size_t)BH*Sc*DHc];
__device__ int g_tile_ctr;

// ------------------------- helpers -------------------------
__device__ __forceinline__ uint32_t smem_u32(const void* p) {
    uint32_t a;
    asm("{ .reg .u64 t; cvta.to.shared.u64 t, %1; cvt.u32.u64 %0, t; }" : "=r"(a) : "l"(p));
    return a;
}
__device__ __forceinline__ void ldsm4(uint32_t* r, uint32_t a) {
    asm volatile("ldmatrix.sync.aligned.m8n8.x4.shared.b16 {%0,%1,%2,%3}, [%4];"
        : "=r"(r[0]), "=r"(r[1]), "=r"(r[2]), "=r"(r[3]) : "r"(a));
}
__device__ __forceinline__ void ldsm4t(uint32_t* r, uint32_t a) {
    asm volatile("ldmatrix.sync.aligned.m8n8.x4.trans.shared.b16 {%0,%1,%2,%3}, [%4];"
        : "=r"(r[0]), "=r"(r[1]), "=r"(r[2]), "=r"(r[3]) : "r"(a));
}
__device__ __forceinline__ void mma16816(float* c, const uint32_t* a, const uint32_t* b) {
    asm volatile("mma.sync.aligned.m16n8k16.row.col.f32.f16.f16.f32 "
        "{%0,%1,%2,%3}, {%4,%5,%6,%7}, {%8,%9}, {%0,%1,%2,%3};"
        : "+f"(c[0]), "+f"(c[1]), "+f"(c[2]), "+f"(c[3])
        : "r"(a[0]), "r"(a[1]), "r"(a[2]), "r"(a[3]), "r"(b[0]), "r"(b[1]));
}
__device__ __forceinline__ uint32_t pkh2(float lo, float hi) {
    uint32_t r; asm("cvt.rn.f16x2.f32 %0, %1, %2;" : "=r"(r) : "f"(hi), "f"(lo)); return r;
}
__device__ __forceinline__ void cpa16(uint32_t s, const void* g) {
    asm volatile("cp.async.cg.shared.global [%0], [%1], 16;" :: "r"(s), "l"(g));
}
#define CP_COMMIT() asm volatile("cp.async.commit_group;" ::: "memory")
#define CP_WAIT0()  asm volatile("cp.async.wait_group 0;" ::: "memory")
#define CP_WAIT1()  asm volatile("cp.async.wait_group 1;" ::: "memory")

// stage a 64x256-half tile into swizzled smem (512B rows, chunk^(row&7))
__device__ __forceinline__ void stage_tile(uint32_t dst, const __half* src, int tid) {
    #pragma unroll
    for (int it = 0; it < 8; ++it) {
        int lin = tid + it * 256;
        int row = lin >> 5, d8 = lin & 31;
        uint32_t o = dst + row * 512 + (uint32_t)((d8 ^ (row & 7)) << 4);
        cpa16(o, src + (size_t)row * 256 + d8 * 8);
    }
}

// ---------------------------------------------------------------------------
// gates: smem-cached weights; writes q,k,v fp16 (head-split) on the fly.
// 2 rows/warp, 2 CTAs/SM.
// ---------------------------------------------------------------------------
#define GATES_SMEM (24576 * 4)
__global__ __launch_bounds__(256, 2) void gates_kernel(
    const float* __restrict__ q, const float* __restrict__ k, const float* __restrict__ v,
    const float* __restrict__ igw, const float* __restrict__ igb,
    const float* __restrict__ fgw, const float* __restrict__ fgb)
{
    extern __shared__ float ws[];
    int tid  = threadIdx.x;
    int warp = tid >> 5;
    int lane = tid & 31;

    #pragma unroll
    for (int it = 0; it < 24; ++it) {
        int idx = tid + it * 256;
        float4 val = (idx < 3072) ? ((const float4*)igw)[idx]
                                  : ((const float4*)fgw)[idx - 3072];
        ((float4*)ws)[idx] = val;
    }
    __syncthreads();

    int row0 = blockIdx.x * 16 + warp * 2;
    float acc[2][8];
    #pragma unroll
    for (int r = 0; r < 2; ++r)
        #pragma unroll
        for (int c = 0; c < 8; ++c) acc[r][c] = 0.f;

    #pragma unroll
    for (int part = 0; part < 3; ++part) {
        const float* bp = (part == 0) ? q : (part == 1) ? k : v;
        __half* outh    = (part == 0) ? g_qh : (part == 1) ? g_kh : g_vh;
        #pragma unroll
        for (int it = 0; it < 8; ++it) {
            int f  = it * 128 + lane * 4;
            int wf = part * 1024 + f;
            float4 wi[4], wg_[4];
            #pragma unroll
            for (int h = 0; h < 4; ++h) {
                wi[h]  = *(const float4*)(ws + h * 3072 + wf);
                wg_[h] = *(const float4*)(ws + 12288 + h * 3072 + wf);
            }
            #pragma unroll
            for (int r = 0; r < 2; ++r) {
                int row = row0 + r;
                float4 x = *(const float4*)(bp + (size_t)row * Ec + f);
                #pragma unroll
                for (int h = 0; h < 4; ++h) {
                    acc[r][h]     += x.x*wi[h].x  + x.y*wi[h].y  + x.z*wi[h].z  + x.w*wi[h].w;
                    acc[r][h + 4] += x.x*wg_[h].x + x.y*wg_[h].y + x.z*wg_[h].z + x.w*wg_[h].w;
                }
                int bb = row >> 11, s = row & (Sc - 1);
                int hh = f >> 8, dd = f & 255;
                __half* dst = outh + ((size_t)(bb * NHc + hh) * Sc + s) * DHc + dd;
                ((__half2*)dst)[0] = __floats2half2_rn(x.x, x.y);
                ((__half2*)dst)[1] = __floats2half2_rn(x.z, x.w);
            }
        }
    }
    #pragma unroll
    for (int o = 16; o; o >>= 1)
        #pragma unroll
        for (int r = 0; r < 2; ++r)
            #pragma unroll
            for (int c = 0; c < 8; ++c)
                acc[r][c] += __shfl_xor_sync(0xffffffffu, acc[r][c], o);

    if (lane < 16) {
        int r = lane >> 3, c = lane & 7;
        float val = 0.f;
        #pragma unroll
        for (int rr = 0; rr < 2; ++rr)
            #pragma unroll
            for (int cc = 0; cc < 8; ++cc)
                if (rr == r && cc == c) val = acc[rr][cc];

        int row = row0 + r;
        int b = row >> 11;
        int s = row & (Sc - 1);
        if (c < 4) {
            g_ig[(b * NHc + c) * Sc + s] = val + igb[c];
        } else {
            int h = c - 4;
            float fgv = val + fgb[h];
            float lsf = fminf(fgv, 0.f) - log1pf(expf(-fabsf(fgv)));
            g_lsf[(b * NHc + h) * Sc + s] = lsf;
        }
    }
}

// ---------------------------------------------------------------------------
// scan: cumsum, m, per-64-tile max, prefix-max, mld; resets tile counter
// ---------------------------------------------------------------------------
__global__ __launch_bounds__(1024) void scan_kernel()
{
    __shared__ float s_a[2048];
    __shared__ float s_b[2048];
    __shared__ float s_cs[2048];

    int bh = blockIdx.x;
    int t  = threadIdx.x;
    const int base = bh * Sc;

    if (bh == 0 && t == 0) g_tile_ctr = 0;

    s_a[t]        = g_lsf[base + t];
    s_a[t + 1024] = g_lsf[base + t + 1024];
    __syncthreads();

    float* src = s_a; float* dst = s_b;
    for (int off = 1; off < 2048; off <<= 1) {
        #pragma unroll
        for (int u = 0; u < 2; ++u) {
            int i = t + (u << 10);
            float val = src[i];
            if (i >= off) val += src[i - off];
            dst[i] = val;
        }
        __syncthreads();
        float* tmp = src; src = dst; dst = tmp;
    }
    s_cs[t]        = src[t];
    s_cs[t + 1024] = src[t + 1024];
    __syncthreads();

    #pragma unroll
    for (int u = 0; u < 2; ++u) {
        int i = t + (u << 10);
        float m = g_ig[base + i] - (i > 0 ? s_cs[i - 1] : 0.f);
        g_m[base + i] = m;
        s_a[i] = m;
    }
    __syncthreads();

    if (t < NRT) {
        float mx = -1e30f;
        #pragma unroll 4
        for (int i = 0; i < KT; ++i) mx = fmaxf(mx, s_a[t * KT + i]);
        g_ct[bh * NRT + t] = mx;
    }
    __syncthreads();

    src = s_a; dst = s_b;
    for (int off = 1; off < 2048; off <<= 1) {
        #pragma unroll
        for (int u = 0; u < 2; ++u) {
            int i = t + (u << 10);
            float val = src[i];
            if (i >= off) val = fmaxf(val, src[i - off]);
            dst[i] = val;
        }
        __syncthreads();
        float* tmp = src; src = dst; dst = tmp;
    }
    #pragma unroll
    for (int u = 0; u < 2; ++u) {
        int i = t + (u << 10);
        g_pm[base + i]  = src[i];
        g_mld[base + i] = s_cs[i] + src[i];
    }
}

// ---------------------------------------------------------------------------
// prep_k16: scale fp16 K in place by exp(m - ct)/16. Reads/writes g_kh (8MB).
// Deterministic: gates rewrites g_kh from inputs before this runs each launch.
// ---------------------------------------------------------------------------
__global__ __launch_bounds__(256) void prep_k16()
{
    int idx  = blockIdx.x * 256 + threadIdx.x;   // uint4 index, 8 halves each
    int grow = idx >> 5;                         // bh*Sc + s
    int bh   = grow >> 11;
    int s    = grow & (Sc - 1);
    float sc = __expf(g_m[grow] - g_ct[bh * NRT + (s >> 6)]) * 0.0625f;
    __half2* p = (__half2*)(g_kh + ((size_t)idx << 3));
    #pragma unroll
    for (int i = 0; i < 4; ++i) {
        float2 f = __half22float2(p[i]);
        p[i] = __floats2half2_rn(f.x * sc, f.y * sc);
    }
}

// ---------------------------------------------------------------------------
// attention (R9): HMMA, persistent CTAs (LPT stealing), interleaved
// QK(jt)+PV(jt-1), K x2 / V x3 / P x2 buffers, split K/V waits.
// ---------------------------------------------------------------------------
#define OQ_  0
#define OK0  32768
#define OK1  65536
#define OV0  98304
#define OV1  131072
#define OV2  163840
#define OPS0 196608
#define OPS1 205824
#define ORS  215040
#define OINV 215552
#define OCT  215808
#define OTIL 215936
#define SMEM_BYTES 216064

__global__ __launch_bounds__(256, 1) void attn_kernel(
    const float* __restrict__ out_w, float* __restrict__ out)
{
    extern __shared__ char smb[];
    const uint32_t sb = smem_u32(smb);

    float* rsA  = (float*)(smb + ORS);
    float* sinv = (float*)(smb + OINV);
    float* sct  = (float*)(smb + OCT);
    int*  stile = (int*)(smb + OTIL);

    const int tid  = threadIdx.x;
    const int wid  = tid >> 5;
    const int lane = tid & 31;

    const int wm = wid & 3;        // m-tile (16 rows)
    const int wn = wid >> 2;       // key half (QK) / dh half (PV)
    const int m0 = wm * 16;
    const int g  = lane >> 2;
    const int tg = lane & 3;
    const int s7 = lane & 7;       // swizzle key

    const int lrow8 = (lane & 7) + 8 * ((lane >> 3) & 1);
    const int lcol8 = (lane >> 4);
    const int bq8   = (lane >> 3);

    const uint32_t vbuf[3] = { sb + OV0, sb + OV1, sb + OV2 };
    const uint32_t kbuf[2] = { sb + OK0, sb + OK1 };
    const uint32_t pbuf[2] = { sb + OPS0, sb + OPS1 };
    const uint32_t pabase0 = ((uint32_t)(m0 + lrow8) * 72 + (uint32_t)lcol8 * 8) * 2;

    for (;;) {
        if (tid == 0) *stile = atomicAdd(&g_tile_ctr, 1);
        __syncthreads();
        const int n = *stile;
        if (n >= NTILES) break;

        const int rt = 31 - (n >> 3);     // largest tiles first
        const int bh = n & 7;
        const int r0 = rt * KT;
        const int b = bh >> 2, h = bh & 3;

        const __half* qG = g_qh + (size_t)bh * Sc * DHc;
        const __half* kG = g_kh + (size_t)bh * Sc * DHc;
        const __half* vG = g_vh + (size_t)bh * Sc * DHc;

        if (tid < NRT) sct[tid] = g_ct[bh * NRT + tid];

        stage_tile(sb + OQ_, qG + (size_t)r0 * DHc, tid);
        stage_tile(kbuf[0], kG, tid);
        CP_COMMIT();                       // group: Q + K(0)
        stage_tile(vbuf[0], vG, tid);
        CP_COMMIT();                       // group: V(0)

        const float pm_g  = g_pm[bh * Sc + r0 + m0 + g];
        const float pm_g8 = g_pm[bh * Sc + r0 + m0 + g + 8];
        float rs0 = 0.f, rs1 = 0.f;
        float o_[64];
        #pragma unroll
        for (int i = 0; i < 64; ++i) o_[i] = 0.f;
        uint32_t qa[64];

        for (int jt = 0; jt <= rt; ++jt) {
            const int t0 = jt * KT;
            const uint32_t okb = kbuf[jt & 1];

            CP_WAIT1();          // K(jt) + V(jt-1) arrived; V(jt) may still fly
            __syncthreads();

            if (jt < rt) {
                stage_tile(kbuf[(jt + 1) & 1], kG + (size_t)(t0 + KT) * DHc, tid);
                CP_COMMIT();
                stage_tile(vbuf[(jt + 1) % 3], vG + (size_t)(t0 + KT) * DHc, tid);
                CP_COMMIT();
            }

            if (jt == 0) {
                uint32_t rbase = sb + OQ_ + (uint32_t)(m0 + lrow8) * 512;
                #pragma unroll
                for (int ks = 0; ks < 16; ++ks)
                    ldsm4(qa + 4 * ks, rbase + (uint32_t)(((lcol8 + 2 * ks) ^ s7) << 4));
            }

            // ======= INTERLEAVED: QK(jt) + PV(jt-1) =======
            float c[16];
            #pragma unroll
            for (int i = 0; i < 16; ++i) c[i] = 0.f;

            const bool havePV = (jt > 0);
            const uint32_t pab = pbuf[(jt + 1) & 1] + pabase0;  // (jt-1)&1
            const uint32_t ovb = vbuf[(jt + 2) % 3];            // (jt-1)%3
            uint32_t pa[4];

            #pragma unroll
            for (int ks2 = 0; ks2 < 8; ++ks2) {
                #pragma unroll
                for (int nt = 0; nt < 4; ++nt) {
                    uint32_t bb[4];
                    uint32_t addr = okb + (uint32_t)(32 * wn + nt * 8 + s7) * 512
                                  + (uint32_t)((((ks2 << 2) + bq8) ^ s7) << 4);
                    ldsm4(bb, addr);
                    mma16816(c + 4 * nt, qa + 8 * ks2,     bb);
                    mma16816(c + 4 * nt, qa + 8 * ks2 + 4, bb + 2);
                }
                if (havePV) {
                    int kst = ks2 >> 1;
                    int hh  = ks2 & 1;
                    if (hh == 0) ldsm4(pa, pab + (uint32_t)kst * 32);
                    uint32_t vrow = ovb + (uint32_t)(lrow8 + kst * 16) * 512;
                    #pragma unroll
                    for (int nn = 0; nn < 4; ++nn) {
                        int ntp = hh * 4 + nn;
                        uint32_t vb[4];
                        ldsm4t(vb, vrow + (uint32_t)(((wn * 16 + ntp * 2 + lcol8) ^ s7) << 4));
                        mma16816(o_ + 4 * (2 * ntp),     pa, vb);
                        mma16816(o_ + 4 * (2 * ntp + 1), pa, vb + 2);
                    }
                }
            }

            // ---------------- epilogue (tile jt): scale/mask/pack P ----------------
            {
                char* psb = smb + (pbuf[jt & 1] - sb);
                float ag  = __expf(sct[jt] - pm_g);
                float ag8 = __expf(sct[jt] - pm_g8);
                bool diag = (jt == rt);
                int rowg = r0 + m0 + g;
                #pragma unroll
                for (int nt = 0; nt < 4; ++nt) {
                    int col = t0 + 32 * wn + nt * 8 + 2 * tg;
                    float v0 = c[4*nt+0] * ag;
                    float v1 = c[4*nt+1] * ag;
                    float v2 = c[4*nt+2] * ag8;
                    float v3 = c[4*nt+3] * ag8;
                    if (diag) {
                        if (col     > rowg)     v0 = 0.f;
                        if (col + 1 > rowg)     v1 = 0.f;
                        if (col     > rowg + 8) v2 = 0.f;
                        if (col + 1 > rowg + 8) v3 = 0.f;
                    }
                    rs0 += v0 + v1;
                    rs1 += v2 + v3;
                    int cl = 32 * wn + nt * 8 + 2 * tg;
                    *(uint32_t*)(psb + ((m0 + g)     * 72 + cl) * 2) = pkh2(v0, v1);
                    *(uint32_t*)(psb + ((m0 + g + 8) * 72 + cl) * 2) = pkh2(v2, v3);
                }
            }
        } // jt

        CP_WAIT0();        // V(rt) definitely arrived
        __syncthreads();   // all warps wrote P(rt); V visible

        // ---------------- final P @ V (tile rt) ----------------
        {
            uint32_t pab = pbuf[rt & 1] + pabase0;
            uint32_t ovb = vbuf[rt % 3];
            #pragma unroll
            for (int kst = 0; kst < 4; ++kst) {
                uint32_t pa[4];
                ldsm4(pa, pab + (uint32_t)kst * 32);
                uint32_t vrow = ovb + (uint32_t)(lrow8 + kst * 16) * 512;
                #pragma unroll
                for (int ntp = 0; ntp < 8; ++ntp) {
                    uint32_t vb[4];
                    ldsm4t(vb, vrow + (uint32_t)(((wn * 16 + ntp * 2 + lcol8) ^ s7) << 4));
                    mma16816(o_ + 4 * (2 * ntp),     pa, vb);
                    mma16816(o_ + 4 * (2 * ntp + 1), pa, vb + 2);
                }
            }
        }

        // ---------------- rowsum reduce + normalizer ----------------
        rs0 += __shfl_xor_sync(0xffffffffu, rs0, 1);
        rs0 += __shfl_xor_sync(0xffffffffu, rs0, 2);
        rs1 += __shfl_xor_sync(0xffffffffu, rs1, 1);
        rs1 += __shfl_xor_sync(0xffffffffu, rs1, 2);
        if (tg == 0) {
            rsA[wn * 64 + m0 + g]     = rs0;
            rsA[wn * 64 + m0 + g + 8] = rs1;
        }
        __syncthreads();
        if (tid < 64) {
            float s = rsA[tid] + rsA[64 + tid];
            float nrm = fmaxf(fabsf(s), __expf(-g_mld[bh * Sc + r0 + tid])) + 1e-8f;
            sinv[tid] = 1.f / nrm;
        }
        __syncthreads();

        // ---------------- O -> H staging (f32, stride 260) ----------------
        {
            float* H = (float*)smb;
            float ivg  = sinv[m0 + g];
            float ivg8 = sinv[m0 + g + 8];
            #pragma unroll
            for (int nt = 0; nt < 16; ++nt) {
                int col = wn * 128 + nt * 8 + 2 * tg;
                H[(m0 + g)     * 260 + col]     = o_[4*nt+0] * ivg;
                H[(m0 + g)     * 260 + col + 1] = o_[4*nt+1] * ivg;
                H[(m0 + g + 8) * 260 + col]     = o_[4*nt+2] * ivg8;
                H[(m0 + g + 8) * 260 + col + 1] = o_[4*nt+3] * ivg8;
            }
        }
        __syncthreads();

        // ---------------- LayerNorm + affine + store ----------------
        {
            const float* H = (const float*)smb;
            int r  = tid >> 2;
            int qd = tid & 3;
            const float* hrow = H + r * 260 + qd * 64;
            float s1 = 0.f;
            #pragma unroll
            for (int i = 0; i < 16; ++i) {
                float4 x = *(const float4*)(hrow + i * 4);
                s1 += x.x + x.y + x.z + x.w;
            }
            s1 += __shfl_xor_sync(0xffffffffu, s1, 1);
            s1 += __shfl_xor_sync(0xffffffffu, s1, 2);
            float mean = s1 * (1.f / 256.f);
            float s2 = 0.f;
            #pragma unroll
            for (int i = 0; i < 16; ++i) {
                float4 x = *(const float4*)(hrow + i * 4);
                float d0 = x.x - mean, d1 = x.y - mean, d2 = x.z - mean, d3 = x.w - mean;
                s2 += d0*d0 + d1*d1 + d2*d2 + d3*d3;
            }
            s2 += __shfl_xor_sync(0xffffffffu, s2, 1);
            s2 += __shfl_xor_sync(0xffffffffu, s2, 2);
            float rstd = rsqrtf(s2 * (1.f / 256.f) + 1e-5f);

            float* dst = out + ((size_t)b * Sc + r0 + r) * Ec + h * DHc + qd * 64;
            const float* ow = out_w + h * DHc + qd * 64;
            #pragma unroll
            for (int i = 0; i < 16; ++i) {
                float4 x = *(const float4*)(hrow + i * 4);
                float4 w = *(const float4*)(ow + i * 4);
                float4 y;
                y.x = (x.x - mean) * rstd * (1.f + w.x);
                y.y = (x.y - mean) * rstd * (1.f + w.y);
                y.z = (x.z - mean) * rstd * (1.f + w.z);
                y.w = (x.w - mean) * rstd * (1.f + w.w);
                *(float4*)(dst + i * 4) = y;
            }
        }
        __syncthreads();
    } // tile loop
}

// ---------------------------------------------------------------------------
extern "C" void kernel_launch(void* const* d_in, const int* in_sizes, int n_in,
                              void* d_out, int out_size)
{
    const float* q   = (const float*)d_in[0];
    const float* k   = (const float*)d_in[1];
    const float* v   = (const float*)d_in[2];
    const float* igw = (const float*)d_in[3];
    const float* igb = (const float*)d_in[4];
    const float* fgw = (const float*)d_in[5];
    const float* fgb = (const float*)d_in[6];
    const float* ow  = (const float*)d_in[7];
    float* out = (float*)d_out;

    cudaFuncSetAttribute(attn_kernel, cudaFuncAttributeMaxDynamicSharedMemorySize, SMEM_BYTES);
    cudaFuncSetAttribute(gates_kernel, cudaFuncAttributeMaxDynamicSharedMemorySize, GATES_SMEM);

    gates_kernel<<<(Bc * Sc) / 16, 256, GATES_SMEM>>>(q, k, v, igw, igb, fgw, fgb);
    scan_kernel<<<BH, 1024>>>();
    prep_k16<<<(BH * Sc * DHc / 8) / 256, 256>>>();
    attn_kernel<<<148, 256, SMEM_BYTES>>>(ow, out);
}